// round 14
// baseline (speedup 1.0000x reference)
#include <cuda_runtime.h>

// x: [B=16, C=256, H=32, W=32] viewed [BC=4096][HW=1024].
// ODE: one CTA/channel, f32x2 + FFMA.SAT, one barrier/layer, parity-trick
// shuffle trees. THIS ROUND: occupancy 4 -> 5 (waves 1.73 -> 1.38) funded by
// moving 2 of 8 x1 pairs to private smem slots (state 32 -> 28 regs).
// Transposes: 64x64 float2 tiles (stable at ~8.6us; left alone).

constexpr int HW = 1024;
constexpr int BC = 4096;
constexpr int NL = 30;

__device__ float g_xt[(size_t)HW * BC];
__device__ float g_yt[(size_t)HW * BC];

typedef unsigned long long u64;

__device__ __forceinline__ u64 pk2(float x, float y) {
    u64 r; asm("mov.b64 %0,{%1,%2};" : "=l"(r) : "f"(x), "f"(y)); return r;
}
__device__ __forceinline__ void upk2(u64 v, float& x, float& y) {
    asm("mov.b64 {%0,%1},%2;" : "=f"(x), "=f"(y) : "l"(v));
}
__device__ __forceinline__ u64 fma2(u64 a, u64 b, u64 c) {
    u64 d; asm("fma.rn.f32x2 %0,%1,%2,%3;" : "=l"(d) : "l"(a), "l"(b), "l"(c)); return d;
}
__device__ __forceinline__ u64 add2(u64 a, u64 b) {
    u64 d; asm("add.rn.f32x2 %0,%1,%2;" : "=l"(d) : "l"(a), "l"(b)); return d;
}
__device__ __forceinline__ u64 mul2(u64 a, u64 b) {
    u64 d; asm("mul.rn.f32x2 %0,%1,%2;" : "=l"(d) : "l"(a), "l"(b)); return d;
}
__device__ __forceinline__ float fma_sat(float a, float b, float c) {
    float d; asm("fma.rn.sat.f32 %0,%1,%2,%3;" : "=f"(d) : "f"(a), "f"(b), "f"(c)); return d;
}

// ---------------------------------------------------------------------------
// float2 tiled transpose, 64x64 tiles (proven, ~8.6us): out[c][r] = in[r][c].
// ---------------------------------------------------------------------------
template<int ROWS, int COLS>
__global__ __launch_bounds__(256) void tr64_kernel(const float* __restrict__ in,
                                                   float* __restrict__ out) {
    __shared__ float tile[64][66];
    const int bx = blockIdx.x * 64;           // column base (in)
    const int by = blockIdx.y * 64;           // row base (in)
    const int t  = threadIdx.x;

    {
        const int tx = t & 31;
        const int ty = t >> 5;
        float2 v[8];
#pragma unroll
        for (int j = 0; j < 8; ++j)
            v[j] = *reinterpret_cast<const float2*>(
                in + (size_t)(by + ty + j * 8) * COLS + bx + tx * 2);
#pragma unroll
        for (int j = 0; j < 8; ++j)
            *reinterpret_cast<float2*>(&tile[ty + j * 8][tx * 2]) = v[j];
    }
    __syncthreads();
    {
        const int tx = t & 15;
        const int ty = t >> 4;
        float2 v[8];
#pragma unroll
        for (int j = 0; j < 4; ++j) {
            const int r = ty + j * 16;
#pragma unroll
            for (int h = 0; h < 2; ++h) {
                const int c2 = tx + 16 * h;
                v[j * 2 + h].x = tile[c2 * 2 + 0][r];
                v[j * 2 + h].y = tile[c2 * 2 + 1][r];
            }
        }
#pragma unroll
        for (int j = 0; j < 4; ++j) {
            const int r = ty + j * 16;
#pragma unroll
            for (int h = 0; h < 2; ++h) {
                const int c2 = tx + 16 * h;
                *reinterpret_cast<float2*>(
                    out + (size_t)(bx + r) * ROWS + by + c2 * 2) = v[j * 2 + h];
            }
        }
    }
}

// ---------------------------------------------------------------------------
// Fused 30-layer ODE. One CTA per channel p, 256 threads, occupancy 5.
// Thread t owns (cij=t, b=0..15): 6 packed pairs in regs + 2 in private
// smem slots. One __syncthreads per layer; parity-trick shuffle trees.
// ---------------------------------------------------------------------------
__global__ __launch_bounds__(256, 5) void ode_kernel(
    const float* __restrict__ xt,        // [HW][BC]
    const float* __restrict__ dtg,       // [NL]
    const float* __restrict__ mats,      // [NL][256]
    const float* __restrict__ gamma,     // [HW]
    const float* __restrict__ beta,      // [HW]
    float* __restrict__ yt)              // [HW][BC]
{
    __shared__ float4 lay[NL];           // {c1_l, A_{l+1}, 6*dt_l*A_{l+1}, eps*A_l^2}
    __shared__ float  red[2][16];        // interleaved s,q per warp
    __shared__ float2 sm_x1[2][256];     // x1 pairs u=6,7 (private slots)
    __shared__ float  sm_alpha;

    const int p = blockIdx.x;
    const int t = threadIdx.x;
    const int lane = t & 31;
    const int wid  = t >> 5;

    // --- per-layer scalar precompute ---
    if (t < NL) {
        float d = dtg[t];
        d = fminf(fmaxf(d, 0.0f), 6.0f);
        lay[t].x = 1.0f - d;             // c1
        lay[t].y = d;                    // stash dt
    }
    __syncthreads();
    if (t == 0) {
        float A = 1.0f;                  // 1/alpha running
        float P = 1.0f;                  // alpha running (prod c1)
        for (int l = 0; l < NL; ++l) {
            const float c1 = lay[l].x;
            const float d  = lay[l].y;
            const float eps = 1e-5f * A * A;
            const float An = __fdividef(A, c1);
            P *= c1;
            lay[l] = make_float4(c1, An, 6.0f * d * An, eps);
            A = An;
        }
        sm_alpha = P;
    }

    const float gm = gamma[p];
    const float bt = beta[p];
    const float* __restrict__ xp = xt + (size_t)p * BC + t;
    const float* __restrict__ mp = mats + t;

    // --- load x1 (6 pairs regs + 2 pairs smem), init z̃_1 = (1+m_0)*x1 ---
    float mt = mp[0];
    u64 x1[6], z[8];
#pragma unroll
    for (int u = 0; u < 8; ++u) {
        const float a = xp[(2 * u) * 256];
        const float b = xp[(2 * u + 1) * 256];
        if (u < 6) x1[u] = pk2(a, b);
        else       sm_x1[u - 6][t] = make_float2(a, b);
        z[u] = pk2(fmaf(mt, a, a), fmaf(mt, b, b));
    }
    __syncthreads();                      // covers lay[] / sm_alpha from t==0

    for (int l = 0; l < NL; ++l) {
        const float4 L = lay[l];          // LDS.128 broadcast
        const float mnx = (l < NL - 1) ? mp[(l + 1) * 256] : 1.0f;
        const float kps = fmaf(-L.x, mt, mnx) * L.y;   // (m' - c1*m) * A_{l+1}
        mt = mnx;
        const u64 kp   = pk2(kps, kps);
        const u64 dt6p = pk2(L.z, L.z);
        const int par  = l & 1;

        // stats on z̃ (packed accumulate)
        u64 s2 = 0ull, q2 = 0ull;
#pragma unroll
        for (int u = 0; u < 8; ++u) {
            s2 = add2(s2, z[u]);
            q2 = fma2(z[u], z[u], q2);
        }
        float sx, sy, qx, qy;
        upk2(s2, sx, sy); upk2(q2, qx, qy);
        const float s = sx + sy, q = qx + qy;

        // parity-merged warp butterfly: 7 shfl.
        const float sn = __shfl_xor_sync(0xffffffffu, s, 1);
        const float qn = __shfl_xor_sync(0xffffffffu, q, 1);
        float v = (lane & 1) ? (q + qn) : (s + sn);
#pragma unroll
        for (int o = 2; o <= 16; o <<= 1)
            v += __shfl_xor_sync(0xffffffffu, v, o);
        if (lane < 2) red[par][wid * 2 + lane] = v;
        __syncthreads();                  // the ONLY barrier this layer

        // final reduce over 16 interleaved partials: 4 shfl.
        float w = red[par][lane & 15];
#pragma unroll
        for (int o = 2; o <= 8; o <<= 1)
            w += __shfl_xor_sync(0xffffffffu, w, o);
        const float wx = __shfl_xor_sync(0xffffffffu, w, 1);
        const float S = (lane & 1) ? wx : w;
        const float Q = (lane & 1) ? w : wx;

        const float inv = 1.0f / 4096.0f;
        const float mu  = S * inv;
        const float va  = fmaf(-mu, mu, Q * inv);
        const float ap  = gm * rsqrtf(va + L.w);
        const float a6  = ap * (1.0f / 6.0f);
        const float b6  = fmaf(-mu, ap, bt) * (1.0f / 6.0f);

#pragma unroll
        for (int u = 0; u < 8; ++u) {
            float zx, zy; upk2(z[u], zx, zy);
            const float rx = fma_sat(zx, a6, b6);      // relu6/6 via FFMA.SAT
            const float ry = fma_sat(zy, a6, b6);
            z[u] = fma2(dt6p, pk2(rx, ry), z[u]);
            u64 xv;
            if (u < 6) {
                xv = x1[u];
            } else {
                const float2 xs = sm_x1[u - 6][t];     // private slot, no sync
                xv = pk2(xs.x, xs.y);
            }
            z[u] = fma2(kp, xv, z[u]);
        }
    }

    // out = alpha * z̃_final  (layer 29 used m'=1 so z̃ holds y + x1)
    const float al = sm_alpha;
    const u64 al2 = pk2(al, al);
    float* __restrict__ yp = yt + (size_t)p * BC + t;
#pragma unroll
    for (int u = 0; u < 8; ++u) {
        float ox, oy; upk2(mul2(z[u], al2), ox, oy);
        yp[(2 * u) * 256]     = ox;
        yp[(2 * u + 1) * 256] = oy;
    }
}

// ---------------------------------------------------------------------------
extern "C" void kernel_launch(void* const* d_in, const int* in_sizes, int n_in,
                              void* d_out, int out_size) {
    const float* x   = (const float*)d_in[0];   // [16,256,32,32]
    const float* dt  = (const float*)d_in[1];   // [30,1]
    const float* mat = (const float*)d_in[2];   // [30,1,1,16,16]
    const float* gm  = (const float*)d_in[3];   // [1024]
    const float* bt  = (const float*)d_in[4];   // [1024]
    float* out = (float*)d_out;                 // [16,256,32,32]

    float *xt, *yt;
    cudaGetSymbolAddress((void**)&xt, g_xt);
    cudaGetSymbolAddress((void**)&yt, g_yt);

    // x: [4096 x 1024] -> xt: [1024 x 4096]
    tr64_kernel<BC, HW><<<dim3(HW / 64, BC / 64), 256>>>(x, xt);
    // fused 30-layer ODE, one CTA per channel, occupancy 5
    ode_kernel<<<HW, 256>>>(xt, dt, mat, gm, bt, yt);
    // yt: [1024 x 4096] -> out: [4096 x 1024]
    tr64_kernel<HW, BC><<<dim3(BC / 64, HW / 64), 256>>>(yt, out);
}

// round 15
// speedup vs baseline: 1.7645x; 1.7645x over previous
#include <cuda_runtime.h>

// x: [B=16, C=256, H=32, W=32] viewed [BC=4096][HW=1024].
// ODE: round-13 proven core (one CTA/channel, occ 4, f32x2 + FFMA.SAT, one
// barrier/layer, parity-trick warp butterfly). THIS ROUND: final cross-warp
// reduce via 4 broadcast LDS.128 + register sum tree (no shuffles) — cuts
// ~70 cyc off the per-layer serial chain.
// Transposes: 64x64 float2 tiles (stable ~8.6us; clock canary).

constexpr int HW = 1024;
constexpr int BC = 4096;
constexpr int NL = 30;

__device__ float g_xt[(size_t)HW * BC];
__device__ float g_yt[(size_t)HW * BC];

typedef unsigned long long u64;

__device__ __forceinline__ u64 pk2(float x, float y) {
    u64 r; asm("mov.b64 %0,{%1,%2};" : "=l"(r) : "f"(x), "f"(y)); return r;
}
__device__ __forceinline__ void upk2(u64 v, float& x, float& y) {
    asm("mov.b64 {%0,%1},%2;" : "=f"(x), "=f"(y) : "l"(v));
}
__device__ __forceinline__ u64 fma2(u64 a, u64 b, u64 c) {
    u64 d; asm("fma.rn.f32x2 %0,%1,%2,%3;" : "=l"(d) : "l"(a), "l"(b), "l"(c)); return d;
}
__device__ __forceinline__ u64 add2(u64 a, u64 b) {
    u64 d; asm("add.rn.f32x2 %0,%1,%2;" : "=l"(d) : "l"(a), "l"(b)); return d;
}
__device__ __forceinline__ u64 mul2(u64 a, u64 b) {
    u64 d; asm("mul.rn.f32x2 %0,%1,%2;" : "=l"(d) : "l"(a), "l"(b)); return d;
}
__device__ __forceinline__ float fma_sat(float a, float b, float c) {
    float d; asm("fma.rn.sat.f32 %0,%1,%2,%3;" : "=f"(d) : "f"(a), "f"(b), "f"(c)); return d;
}

// ---------------------------------------------------------------------------
// float2 tiled transpose, 64x64 tiles (proven): out[c][r] = in[r][c].
// ---------------------------------------------------------------------------
template<int ROWS, int COLS>
__global__ __launch_bounds__(256) void tr64_kernel(const float* __restrict__ in,
                                                   float* __restrict__ out) {
    __shared__ float tile[64][66];
    const int bx = blockIdx.x * 64;           // column base (in)
    const int by = blockIdx.y * 64;           // row base (in)
    const int t  = threadIdx.x;

    {
        const int tx = t & 31;
        const int ty = t >> 5;
        float2 v[8];
#pragma unroll
        for (int j = 0; j < 8; ++j)
            v[j] = *reinterpret_cast<const float2*>(
                in + (size_t)(by + ty + j * 8) * COLS + bx + tx * 2);
#pragma unroll
        for (int j = 0; j < 8; ++j)
            *reinterpret_cast<float2*>(&tile[ty + j * 8][tx * 2]) = v[j];
    }
    __syncthreads();
    {
        const int tx = t & 15;
        const int ty = t >> 4;
        float2 v[8];
#pragma unroll
        for (int j = 0; j < 4; ++j) {
            const int r = ty + j * 16;
#pragma unroll
            for (int h = 0; h < 2; ++h) {
                const int c2 = tx + 16 * h;
                v[j * 2 + h].x = tile[c2 * 2 + 0][r];
                v[j * 2 + h].y = tile[c2 * 2 + 1][r];
            }
        }
#pragma unroll
        for (int j = 0; j < 4; ++j) {
            const int r = ty + j * 16;
#pragma unroll
            for (int h = 0; h < 2; ++h) {
                const int c2 = tx + 16 * h;
                *reinterpret_cast<float2*>(
                    out + (size_t)(bx + r) * ROWS + by + c2 * 2) = v[j * 2 + h];
            }
        }
    }
}

// ---------------------------------------------------------------------------
// Fused 30-layer ODE. One CTA per channel p, 256 threads, occupancy 4.
// Thread t owns (cij=t, b=0..15) as 8 packed pairs; x1 and z in registers.
// One __syncthreads per layer; parity-trick warp butterfly (7 shfl), then
// final cross-warp reduce via 4 broadcast LDS.128 + register sum tree.
// ---------------------------------------------------------------------------
__global__ __launch_bounds__(256, 4) void ode_kernel(
    const float* __restrict__ xt,        // [HW][BC]
    const float* __restrict__ dtg,       // [NL]
    const float* __restrict__ mats,      // [NL][256]
    const float* __restrict__ gamma,     // [HW]
    const float* __restrict__ beta,      // [HW]
    float* __restrict__ yt)              // [HW][BC]
{
    __shared__ float4 lay[NL];           // {c1_l, A_{l+1}, 6*dt_l*A_{l+1}, eps*A_l^2}
    __shared__ __align__(16) float red[2][16];   // interleaved s0,q0,s1,q1,... per warp
    __shared__ float sm_alpha;

    const int p = blockIdx.x;
    const int t = threadIdx.x;
    const int lane = t & 31;
    const int wid  = t >> 5;

    // --- per-layer scalar precompute ---
    if (t < NL) {
        float d = dtg[t];
        d = fminf(fmaxf(d, 0.0f), 6.0f);
        lay[t].x = 1.0f - d;             // c1
        lay[t].y = d;                    // stash dt
    }
    __syncthreads();
    if (t == 0) {
        float A = 1.0f;                  // 1/alpha running
        float P = 1.0f;                  // alpha running (prod c1)
        for (int l = 0; l < NL; ++l) {
            const float c1 = lay[l].x;
            const float d  = lay[l].y;
            const float eps = 1e-5f * A * A;
            const float An = __fdividef(A, c1);
            P *= c1;
            lay[l] = make_float4(c1, An, 6.0f * d * An, eps);
            A = An;
        }
        sm_alpha = P;
    }

    const float gm = gamma[p];
    const float bt = beta[p];
    const float* __restrict__ xp = xt + (size_t)p * BC + t;
    const float* __restrict__ mp = mats + t;

    // --- load x1 to registers, init z̃_1 = (1+m_0)*x1 ---
    float mt = mp[0];
    u64 x1[8], z[8];
#pragma unroll
    for (int u = 0; u < 8; ++u) {
        const float a = xp[(2 * u) * 256];
        const float b = xp[(2 * u + 1) * 256];
        x1[u] = pk2(a, b);
        z[u]  = pk2(fmaf(mt, a, a), fmaf(mt, b, b));
    }
    __syncthreads();                      // covers lay[] / sm_alpha from t==0

    for (int l = 0; l < NL; ++l) {
        const float4 L = lay[l];          // LDS.128 broadcast
        const float mnx = (l < NL - 1) ? mp[(l + 1) * 256] : 1.0f;
        const float kps = fmaf(-L.x, mt, mnx) * L.y;   // (m' - c1*m) * A_{l+1}
        mt = mnx;
        const u64 kp   = pk2(kps, kps);
        const u64 dt6p = pk2(L.z, L.z);
        const int par  = l & 1;

        // stats on z̃ (packed accumulate)
        u64 s2 = 0ull, q2 = 0ull;
#pragma unroll
        for (int u = 0; u < 8; ++u) {
            s2 = add2(s2, z[u]);
            q2 = fma2(z[u], z[u], q2);
        }
        float sx, sy, qx, qy;
        upk2(s2, sx, sy); upk2(q2, qx, qy);
        const float s = sx + sy, q = qx + qy;

        // parity-merged warp butterfly: 7 shfl.
        const float sn = __shfl_xor_sync(0xffffffffu, s, 1);
        const float qn = __shfl_xor_sync(0xffffffffu, q, 1);
        float v = (lane & 1) ? (q + qn) : (s + sn);
#pragma unroll
        for (int o = 2; o <= 16; o <<= 1)
            v += __shfl_xor_sync(0xffffffffu, v, o);
        if (lane < 2) red[par][wid * 2 + lane] = v;   // s at even idx, q at odd
        __syncthreads();                  // the ONLY barrier this layer

        // final reduce: 4 broadcast LDS.128 + pairwise register sums
        const float4* __restrict__ rp = reinterpret_cast<const float4*>(red[par]);
        const float4 r0 = rp[0], r1 = rp[1], r2 = rp[2], r3 = rp[3];
        const float S = ((r0.x + r1.x) + (r2.x + r3.x)) +
                        ((r0.z + r1.z) + (r2.z + r3.z));
        const float Q = ((r0.y + r1.y) + (r2.y + r3.y)) +
                        ((r0.w + r1.w) + (r2.w + r3.w));

        const float inv = 1.0f / 4096.0f;
        const float mu  = S * inv;
        const float va  = fmaf(-mu, mu, Q * inv);
        const float ap  = gm * rsqrtf(va + L.w);
        const float a6  = ap * (1.0f / 6.0f);
        const float b6  = fmaf(-mu, ap, bt) * (1.0f / 6.0f);

#pragma unroll
        for (int u = 0; u < 8; ++u) {
            float zx, zy; upk2(z[u], zx, zy);
            const float rx = fma_sat(zx, a6, b6);      // relu6/6 via FFMA.SAT
            const float ry = fma_sat(zy, a6, b6);
            z[u] = fma2(dt6p, pk2(rx, ry), z[u]);
            z[u] = fma2(kp, x1[u], z[u]);
        }
    }

    // out = alpha * z̃_final  (layer 29 used m'=1 so z̃ holds y + x1)
    const float al = sm_alpha;
    const u64 al2 = pk2(al, al);
    float* __restrict__ yp = yt + (size_t)p * BC + t;
#pragma unroll
    for (int u = 0; u < 8; ++u) {
        float ox, oy; upk2(mul2(z[u], al2), ox, oy);
        yp[(2 * u) * 256]     = ox;
        yp[(2 * u + 1) * 256] = oy;
    }
}

// ---------------------------------------------------------------------------
extern "C" void kernel_launch(void* const* d_in, const int* in_sizes, int n_in,
                              void* d_out, int out_size) {
    const float* x   = (const float*)d_in[0];   // [16,256,32,32]
    const float* dt  = (const float*)d_in[1];   // [30,1]
    const float* mat = (const float*)d_in[2];   // [30,1,1,16,16]
    const float* gm  = (const float*)d_in[3];   // [1024]
    const float* bt  = (const float*)d_in[4];   // [1024]
    float* out = (float*)d_out;                 // [16,256,32,32]

    float *xt, *yt;
    cudaGetSymbolAddress((void**)&xt, g_xt);
    cudaGetSymbolAddress((void**)&yt, g_yt);

    // x: [4096 x 1024] -> xt: [1024 x 4096]
    tr64_kernel<BC, HW><<<dim3(HW / 64, BC / 64), 256>>>(x, xt);
    // fused 30-layer ODE, one CTA per channel, occupancy 4
    ode_kernel<<<HW, 256>>>(xt, dt, mat, gm, bt, yt);
    // yt: [1024 x 4096] -> out: [4096 x 1024]
    tr64_kernel<HW, BC><<<dim3(BC / 64, HW / 64), 256>>>(yt, out);
}

// round 16
// speedup vs baseline: 1.7719x; 1.0042x over previous
#include <cuda_runtime.h>

// x: [B=16, C=256, H=32, W=32] viewed [BC=4096][HW=1024].
// ODE: round-13 proven core exact (one CTA/channel, occ 4, f32x2 + FFMA.SAT,
// one barrier/layer, parity-trick butterfly + 4-shfl final reduce).
// Transposes: TWO 64x64 float2 tiles per CTA (proven stride-66 pattern),
// 16 LDG.64 = 128B in flight per thread -> lifts the latency*MLP ceiling.

constexpr int HW = 1024;
constexpr int BC = 4096;
constexpr int NL = 30;

__device__ float g_xt[(size_t)HW * BC];
__device__ float g_yt[(size_t)HW * BC];

typedef unsigned long long u64;

__device__ __forceinline__ u64 pk2(float x, float y) {
    u64 r; asm("mov.b64 %0,{%1,%2};" : "=l"(r) : "f"(x), "f"(y)); return r;
}
__device__ __forceinline__ void upk2(u64 v, float& x, float& y) {
    asm("mov.b64 {%0,%1},%2;" : "=f"(x), "=f"(y) : "l"(v));
}
__device__ __forceinline__ u64 fma2(u64 a, u64 b, u64 c) {
    u64 d; asm("fma.rn.f32x2 %0,%1,%2,%3;" : "=l"(d) : "l"(a), "l"(b), "l"(c)); return d;
}
__device__ __forceinline__ u64 add2(u64 a, u64 b) {
    u64 d; asm("add.rn.f32x2 %0,%1,%2;" : "=l"(d) : "l"(a), "l"(b)); return d;
}
__device__ __forceinline__ u64 mul2(u64 a, u64 b) {
    u64 d; asm("mul.rn.f32x2 %0,%1,%2;" : "=l"(d) : "l"(a), "l"(b)); return d;
}
__device__ __forceinline__ float fma_sat(float a, float b, float c) {
    float d; asm("fma.rn.sat.f32 %0,%1,%2,%3;" : "=f"(d) : "f"(a), "f"(b), "f"(c)); return d;
}

// ---------------------------------------------------------------------------
// float2 tiled transpose, TWO 64x64 tiles per CTA (rows by..by+127).
// tile[tt][64][66]: even stride -> aligned float2 smem ops (proven pattern).
// ALL 16 LDG.64 issued before any STS -> 128B in flight per thread.
// ---------------------------------------------------------------------------
template<int ROWS, int COLS>
__global__ __launch_bounds__(256) void tr64x2_kernel(const float* __restrict__ in,
                                                     float* __restrict__ out) {
    __shared__ float tile[2][64][66];
    const int bx = blockIdx.x * 64;            // column base (in)
    const int by = blockIdx.y * 128;           // row base (in), 2 tiles
    const int t  = threadIdx.x;

    {
        const int tx = t & 31;                 // float2 index across 64 cols
        const int ty = t >> 5;                 // 8 rows per step
        float2 v[16];
#pragma unroll
        for (int tt = 0; tt < 2; ++tt)         // ALL 16 loads first (MLP = 16)
#pragma unroll
            for (int j = 0; j < 8; ++j)
                v[tt * 8 + j] = *reinterpret_cast<const float2*>(
                    in + (size_t)(by + tt * 64 + ty + j * 8) * COLS + bx + tx * 2);
#pragma unroll
        for (int tt = 0; tt < 2; ++tt)
#pragma unroll
            for (int j = 0; j < 8; ++j)
                *reinterpret_cast<float2*>(&tile[tt][ty + j * 8][tx * 2]) = v[tt * 8 + j];
    }
    __syncthreads();
    {
        const int tx = t & 15;                 // float2 index (half of 32)
        const int ty = t >> 4;                 // 16 out-rows per step
        float2 w[16];
#pragma unroll
        for (int tt = 0; tt < 2; ++tt)
#pragma unroll
            for (int j = 0; j < 4; ++j) {
                const int r = ty + j * 16;
#pragma unroll
                for (int h = 0; h < 2; ++h) {
                    const int c2 = tx + 16 * h;
                    float2& wv = w[tt * 8 + j * 2 + h];
                    wv.x = tile[tt][c2 * 2 + 0][r];
                    wv.y = tile[tt][c2 * 2 + 1][r];
                }
            }
#pragma unroll
        for (int tt = 0; tt < 2; ++tt)
#pragma unroll
            for (int j = 0; j < 4; ++j) {
                const int r = ty + j * 16;
#pragma unroll
                for (int h = 0; h < 2; ++h) {
                    const int c2 = tx + 16 * h;
                    *reinterpret_cast<float2*>(
                        out + (size_t)(bx + r) * ROWS + by + tt * 64 + c2 * 2)
                        = w[tt * 8 + j * 2 + h];
                }
            }
    }
}

// ---------------------------------------------------------------------------
// Fused 30-layer ODE (round-13 proven, exact). One CTA per channel p,
// 256 threads, occ 4. One barrier/layer; parity-trick shuffle trees (7+4).
// ---------------------------------------------------------------------------
__global__ __launch_bounds__(256, 4) void ode_kernel(
    const float* __restrict__ xt,        // [HW][BC]
    const float* __restrict__ dtg,       // [NL]
    const float* __restrict__ mats,      // [NL][256]
    const float* __restrict__ gamma,     // [HW]
    const float* __restrict__ beta,      // [HW]
    float* __restrict__ yt)              // [HW][BC]
{
    __shared__ float4 lay[NL];           // {c1_l, A_{l+1}, 6*dt_l*A_{l+1}, eps*A_l^2}
    __shared__ float  red[2][16];        // interleaved s0,q0,s1,q1,... per warp
    __shared__ float  sm_alpha;

    const int p = blockIdx.x;
    const int t = threadIdx.x;
    const int lane = t & 31;
    const int wid  = t >> 5;

    if (t < NL) {
        float d = dtg[t];
        d = fminf(fmaxf(d, 0.0f), 6.0f);
        lay[t].x = 1.0f - d;             // c1
        lay[t].y = d;                    // stash dt
    }
    __syncthreads();
    if (t == 0) {
        float A = 1.0f;                  // 1/alpha running
        float P = 1.0f;                  // alpha running (prod c1)
        for (int l = 0; l < NL; ++l) {
            const float c1 = lay[l].x;
            const float d  = lay[l].y;
            const float eps = 1e-5f * A * A;
            const float An = __fdividef(A, c1);
            P *= c1;
            lay[l] = make_float4(c1, An, 6.0f * d * An, eps);
            A = An;
        }
        sm_alpha = P;
    }

    const float gm = gamma[p];
    const float bt = beta[p];
    const float* __restrict__ xp = xt + (size_t)p * BC + t;
    const float* __restrict__ mp = mats + t;

    float mt = mp[0];
    u64 x1[8], z[8];
#pragma unroll
    for (int u = 0; u < 8; ++u) {
        const float a = xp[(2 * u) * 256];
        const float b = xp[(2 * u + 1) * 256];
        x1[u] = pk2(a, b);
        z[u]  = pk2(fmaf(mt, a, a), fmaf(mt, b, b));
    }
    __syncthreads();                      // covers lay[] / sm_alpha from t==0

    for (int l = 0; l < NL; ++l) {
        const float4 L = lay[l];          // LDS.128 broadcast
        const float mnx = (l < NL - 1) ? mp[(l + 1) * 256] : 1.0f;
        const float kps = fmaf(-L.x, mt, mnx) * L.y;   // (m' - c1*m) * A_{l+1}
        mt = mnx;
        const u64 kp   = pk2(kps, kps);
        const u64 dt6p = pk2(L.z, L.z);
        const int par  = l & 1;

        u64 s2 = 0ull, q2 = 0ull;
#pragma unroll
        for (int u = 0; u < 8; ++u) {
            s2 = add2(s2, z[u]);
            q2 = fma2(z[u], z[u], q2);
        }
        float sx, sy, qx, qy;
        upk2(s2, sx, sy); upk2(q2, qx, qy);
        const float s = sx + sy, q = qx + qy;

        // parity-merged warp butterfly: 7 shfl.
        const float sn = __shfl_xor_sync(0xffffffffu, s, 1);
        const float qn = __shfl_xor_sync(0xffffffffu, q, 1);
        float v = (lane & 1) ? (q + qn) : (s + sn);
#pragma unroll
        for (int o = 2; o <= 16; o <<= 1)
            v += __shfl_xor_sync(0xffffffffu, v, o);
        if (lane < 2) red[par][wid * 2 + lane] = v;
        __syncthreads();                  // the ONLY barrier this layer

        // final reduce over 16 interleaved partials: 4 shfl.
        float w = red[par][lane & 15];
#pragma unroll
        for (int o = 2; o <= 8; o <<= 1)
            w += __shfl_xor_sync(0xffffffffu, w, o);
        const float wx = __shfl_xor_sync(0xffffffffu, w, 1);
        const float S = (lane & 1) ? wx : w;
        const float Q = (lane & 1) ? w : wx;

        const float inv = 1.0f / 4096.0f;
        const float mu  = S * inv;
        const float va  = fmaf(-mu, mu, Q * inv);
        const float ap  = gm * rsqrtf(va + L.w);
        const float a6  = ap * (1.0f / 6.0f);
        const float b6  = fmaf(-mu, ap, bt) * (1.0f / 6.0f);

#pragma unroll
        for (int u = 0; u < 8; ++u) {
            float zx, zy; upk2(z[u], zx, zy);
            const float rx = fma_sat(zx, a6, b6);      // relu6/6 via FFMA.SAT
            const float ry = fma_sat(zy, a6, b6);
            z[u] = fma2(dt6p, pk2(rx, ry), z[u]);
            z[u] = fma2(kp, x1[u], z[u]);
        }
    }

    // out = alpha * z̃_final  (layer 29 used m'=1 so z̃ holds y + x1)
    const float al = sm_alpha;
    const u64 al2 = pk2(al, al);
    float* __restrict__ yp = yt + (size_t)p * BC + t;
#pragma unroll
    for (int u = 0; u < 8; ++u) {
        float ox, oy; upk2(mul2(z[u], al2), ox, oy);
        yp[(2 * u) * 256]     = ox;
        yp[(2 * u + 1) * 256] = oy;
    }
}

// ---------------------------------------------------------------------------
extern "C" void kernel_launch(void* const* d_in, const int* in_sizes, int n_in,
                              void* d_out, int out_size) {
    const float* x   = (const float*)d_in[0];   // [16,256,32,32]
    const float* dt  = (const float*)d_in[1];   // [30,1]
    const float* mat = (const float*)d_in[2];   // [30,1,1,16,16]
    const float* gm  = (const float*)d_in[3];   // [1024]
    const float* bt  = (const float*)d_in[4];   // [1024]
    float* out = (float*)d_out;                 // [16,256,32,32]

    float *xt, *yt;
    cudaGetSymbolAddress((void**)&xt, g_xt);
    cudaGetSymbolAddress((void**)&yt, g_yt);

    // x: [4096 x 1024] -> xt: [1024 x 4096]   (grid 16 x 32 = 512 CTAs)
    tr64x2_kernel<BC, HW><<<dim3(HW / 64, BC / 128), 256>>>(x, xt);
    // fused 30-layer ODE, one CTA per channel
    ode_kernel<<<HW, 256>>>(xt, dt, mat, gm, bt, yt);
    // yt: [1024 x 4096] -> out: [4096 x 1024] (grid 64 x 8 = 512 CTAs)
    tr64x2_kernel<HW, BC><<<dim3(BC / 64, HW / 128), 256>>>(yt, out);
}

// round 17
// speedup vs baseline: 1.8398x; 1.0383x over previous
#include <cuda_runtime.h>

// x: [B=16, C=256, H=32, W=32] viewed [BC=4096][HW=1024].
// ODE: round-13 core + (a) mats preloaded to smem (kills per-layer gmem
// dependency), (b) tree-reduced pass-1 accumulators (shorter chain).
// Transposes: tr64 proven 64x64 float2 tiles (~8.5us each).

constexpr int HW = 1024;
constexpr int BC = 4096;
constexpr int NL = 30;

__device__ float g_xt[(size_t)HW * BC];
__device__ float g_yt[(size_t)HW * BC];

typedef unsigned long long u64;

__device__ __forceinline__ u64 pk2(float x, float y) {
    u64 r; asm("mov.b64 %0,{%1,%2};" : "=l"(r) : "f"(x), "f"(y)); return r;
}
__device__ __forceinline__ void upk2(u64 v, float& x, float& y) {
    asm("mov.b64 {%0,%1},%2;" : "=f"(x), "=f"(y) : "l"(v));
}
__device__ __forceinline__ u64 fma2(u64 a, u64 b, u64 c) {
    u64 d; asm("fma.rn.f32x2 %0,%1,%2,%3;" : "=l"(d) : "l"(a), "l"(b), "l"(c)); return d;
}
__device__ __forceinline__ u64 add2(u64 a, u64 b) {
    u64 d; asm("add.rn.f32x2 %0,%1,%2;" : "=l"(d) : "l"(a), "l"(b)); return d;
}
__device__ __forceinline__ u64 mul2(u64 a, u64 b) {
    u64 d; asm("mul.rn.f32x2 %0,%1,%2;" : "=l"(d) : "l"(a), "l"(b)); return d;
}
__device__ __forceinline__ float fma_sat(float a, float b, float c) {
    float d; asm("fma.rn.sat.f32 %0,%1,%2,%3;" : "=f"(d) : "f"(a), "f"(b), "f"(c)); return d;
}

// ---------------------------------------------------------------------------
// float2 tiled transpose, 64x64 tiles (proven): out[c][r] = in[r][c].
// ---------------------------------------------------------------------------
template<int ROWS, int COLS>
__global__ __launch_bounds__(256) void tr64_kernel(const float* __restrict__ in,
                                                   float* __restrict__ out) {
    __shared__ float tile[64][66];
    const int bx = blockIdx.x * 64;           // column base (in)
    const int by = blockIdx.y * 64;           // row base (in)
    const int t  = threadIdx.x;

    {
        const int tx = t & 31;
        const int ty = t >> 5;
        float2 v[8];
#pragma unroll
        for (int j = 0; j < 8; ++j)
            v[j] = *reinterpret_cast<const float2*>(
                in + (size_t)(by + ty + j * 8) * COLS + bx + tx * 2);
#pragma unroll
        for (int j = 0; j < 8; ++j)
            *reinterpret_cast<float2*>(&tile[ty + j * 8][tx * 2]) = v[j];
    }
    __syncthreads();
    {
        const int tx = t & 15;
        const int ty = t >> 4;
        float2 v[8];
#pragma unroll
        for (int j = 0; j < 4; ++j) {
            const int r = ty + j * 16;
#pragma unroll
            for (int h = 0; h < 2; ++h) {
                const int c2 = tx + 16 * h;
                v[j * 2 + h].x = tile[c2 * 2 + 0][r];
                v[j * 2 + h].y = tile[c2 * 2 + 1][r];
            }
        }
#pragma unroll
        for (int j = 0; j < 4; ++j) {
            const int r = ty + j * 16;
#pragma unroll
            for (int h = 0; h < 2; ++h) {
                const int c2 = tx + 16 * h;
                *reinterpret_cast<float2*>(
                    out + (size_t)(bx + r) * ROWS + by + c2 * 2) = v[j * 2 + h];
            }
        }
    }
}

// ---------------------------------------------------------------------------
// Fused 30-layer ODE. One CTA per channel p, 256 threads, occ 4.
// Thread t owns (cij=t, b=0..15) as 8 packed pairs; x1 and z in registers.
// mats preloaded to smem; tree-reduced accumulators; one barrier/layer;
// parity-trick shuffle trees (round-13 structure).
// ---------------------------------------------------------------------------
__global__ __launch_bounds__(256, 4) void ode_kernel(
    const float* __restrict__ xt,        // [HW][BC]
    const float* __restrict__ dtg,       // [NL]
    const float* __restrict__ mats,      // [NL][256]
    const float* __restrict__ gamma,     // [HW]
    const float* __restrict__ beta,      // [HW]
    float* __restrict__ yt)              // [HW][BC]
{
    __shared__ float4 lay[NL];           // {c1_l, A_{l+1}, 6*dt_l*A_{l+1}, eps*A_l^2}
    __shared__ float  sm_m[NL * 256];    // matrices, 30KB
    __shared__ float  red[2][16];        // interleaved s0,q0,s1,q1,... per warp
    __shared__ float  sm_alpha;

    const int p = blockIdx.x;
    const int t = threadIdx.x;
    const int lane = t & 31;
    const int wid  = t >> 5;

    // --- preload mats to smem (coalesced, latency-batched) ---
#pragma unroll
    for (int i = 0; i < NL; ++i)
        sm_m[i * 256 + t] = mats[i * 256 + t];

    // --- per-layer scalar precompute ---
    if (t < NL) {
        float d = dtg[t];
        d = fminf(fmaxf(d, 0.0f), 6.0f);
        lay[t].x = 1.0f - d;             // c1
        lay[t].y = d;                    // stash dt
    }
    __syncthreads();
    if (t == 0) {
        float A = 1.0f;                  // 1/alpha running
        float P = 1.0f;                  // alpha running (prod c1)
        for (int l = 0; l < NL; ++l) {
            const float c1 = lay[l].x;
            const float d  = lay[l].y;
            const float eps = 1e-5f * A * A;
            const float An = __fdividef(A, c1);
            P *= c1;
            lay[l] = make_float4(c1, An, 6.0f * d * An, eps);
            A = An;
        }
        sm_alpha = P;
    }

    const float gm = gamma[p];
    const float bt = beta[p];
    const float* __restrict__ xp = xt + (size_t)p * BC + t;

    // --- load x1 to registers, init z̃_1 = (1+m_0)*x1 ---
    float mt = sm_m[t];                  // valid: sm_m written by this thread pre-sync?
    // (sm_m[t] was written by thread t itself above, so no race; lay needs sync)
    u64 x1[8], z[8];
#pragma unroll
    for (int u = 0; u < 8; ++u) {
        const float a = xp[(2 * u) * 256];
        const float b = xp[(2 * u + 1) * 256];
        x1[u] = pk2(a, b);
        z[u]  = pk2(fmaf(mt, a, a), fmaf(mt, b, b));
    }
    __syncthreads();                      // covers lay[] / sm_alpha from t==0

    for (int l = 0; l < NL; ++l) {
        const float4 L = lay[l];          // LDS.128 broadcast
        const float mnx = (l < NL - 1) ? sm_m[(l + 1) * 256 + t] : 1.0f;
        const float kps = fmaf(-L.x, mt, mnx) * L.y;   // (m' - c1*m) * A_{l+1}
        mt = mnx;
        const u64 kp   = pk2(kps, kps);
        const u64 dt6p = pk2(L.z, L.z);
        const int par  = l & 1;

        // stats on z̃: tree-reduced packed accumulate (depth ~4)
        u64 sA = add2(z[0], z[1]);
        u64 sB = add2(z[2], z[3]);
        u64 sC = add2(z[4], z[5]);
        u64 sD = add2(z[6], z[7]);
        sA = add2(sA, sB);
        sC = add2(sC, sD);
        sA = add2(sA, sC);

        u64 qA = fma2(z[1], z[1], mul2(z[0], z[0]));
        u64 qB = fma2(z[3], z[3], mul2(z[2], z[2]));
        u64 qC = fma2(z[5], z[5], mul2(z[4], z[4]));
        u64 qD = fma2(z[7], z[7], mul2(z[6], z[6]));
        qA = add2(qA, qB);
        qC = add2(qC, qD);
        qA = add2(qA, qC);

        float sx, sy, qx, qy;
        upk2(sA, sx, sy); upk2(qA, qx, qy);
        const float s = sx + sy, q = qx + qy;

        // parity-merged warp butterfly.
        const float sn = __shfl_xor_sync(0xffffffffu, s, 1);
        const float qn = __shfl_xor_sync(0xffffffffu, q, 1);
        float v = (lane & 1) ? (q + qn) : (s + sn);
#pragma unroll
        for (int o = 2; o <= 16; o <<= 1)
            v += __shfl_xor_sync(0xffffffffu, v, o);
        if (lane < 2) red[par][wid * 2 + lane] = v;   // s at even idx, q at odd
        __syncthreads();                  // the ONLY barrier this layer

        // final reduce over 16 interleaved partials.
        float w = red[par][lane & 15];
#pragma unroll
        for (int o = 2; o <= 8; o <<= 1)
            w += __shfl_xor_sync(0xffffffffu, w, o);
        const float wx = __shfl_xor_sync(0xffffffffu, w, 1);
        const float S = (lane & 1) ? wx : w;
        const float Q = (lane & 1) ? w : wx;

        const float inv = 1.0f / 4096.0f;
        const float mu  = S * inv;
        const float va  = fmaf(-mu, mu, Q * inv);
        const float ap  = gm * rsqrtf(va + L.w);
        const float a6  = ap * (1.0f / 6.0f);
        const float b6  = fmaf(-mu, ap, bt) * (1.0f / 6.0f);

#pragma unroll
        for (int u = 0; u < 8; ++u) {
            float zx, zy; upk2(z[u], zx, zy);
            const float rx = fma_sat(zx, a6, b6);      // relu6/6 via FFMA.SAT
            const float ry = fma_sat(zy, a6, b6);
            z[u] = fma2(dt6p, pk2(rx, ry), z[u]);
            z[u] = fma2(kp, x1[u], z[u]);
        }
    }

    // out = alpha * z̃_final  (layer 29 used m'=1 so z̃ holds y + x1)
    const float al = sm_alpha;
    const u64 al2 = pk2(al, al);
    float* __restrict__ yp = yt + (size_t)p * BC + t;
#pragma unroll
    for (int u = 0; u < 8; ++u) {
        float ox, oy; upk2(mul2(z[u], al2), ox, oy);
        yp[(2 * u) * 256]     = ox;
        yp[(2 * u + 1) * 256] = oy;
    }
}

// ---------------------------------------------------------------------------
extern "C" void kernel_launch(void* const* d_in, const int* in_sizes, int n_in,
                              void* d_out, int out_size) {
    const float* x   = (const float*)d_in[0];   // [16,256,32,32]
    const float* dt  = (const float*)d_in[1];   // [30,1]
    const float* mat = (const float*)d_in[2];   // [30,1,1,16,16]
    const float* gm  = (const float*)d_in[3];   // [1024]
    const float* bt  = (const float*)d_in[4];   // [1024]
    float* out = (float*)d_out;                 // [16,256,32,32]

    float *xt, *yt;
    cudaGetSymbolAddress((void**)&xt, g_xt);
    cudaGetSymbolAddress((void**)&yt, g_yt);

    // x: [4096 x 1024] -> xt: [1024 x 4096]
    tr64_kernel<BC, HW><<<dim3(HW / 64, BC / 64), 256>>>(x, xt);
    // fused 30-layer ODE, one CTA per channel
    ode_kernel<<<HW, 256>>>(xt, dt, mat, gm, bt, yt);
    // yt: [1024 x 4096] -> out: [4096 x 1024]
    tr64_kernel<HW, BC><<<dim3(BC / 64, HW / 64), 256>>>(yt, out);
}